// round 6
// baseline (speedup 1.0000x reference)
// NerfMLP on GB300 (sm_103a harness, but PTX target is compute_103 — NO tcgen05).
// Baseline-PTX tensor-core design:
//  - mma.sync.aligned.m16n8k16.row.col.f32.bf16.bf16.f32 (HMMA, sm_80+ PTX)
//  - 3-term bf16 hi/lo split for fp32-grade accuracy, fp32 accumulators
//  - activations live in registers across all 7 layers (C-frag == A-frag layout)
//  - bias folded into accumulator init; epilogue = ReLU + split only
//  - weights pre-staged in SMEM in per-lane fragment layout (conflict-free LDS.64)
//  - persistent CTAs, 256 threads, warp owns 32 rows x 64 cols, tile M=256
//  - no __syncthreads in the tile loop; head output staged per-warp (__syncwarp)

#include <cuda_runtime.h>
#include <cuda_bf16.h>
#include <cstdint>

#define TILE_M 256

// SMEM layout (bytes)
#define OFF_BH    0          // uint2 BH[7*4*8*32] = 57344
#define OFF_BL    57344      // uint2 BL[...]      = 57344
#define OFF_BIAS  114688     // float [7*64]       = 1792
#define OFF_STEMW 116480     // float [96]
#define OFF_STEMB 116864     // float [32]
#define OFF_OUT   116992     // float [256*33]     = 33792
#define SMEM_BYTES 150784

__device__ __forceinline__ void mma_bf16(float& c0, float& c1, float& c2, float& c3,
                                         uint32_t a0, uint32_t a1, uint32_t a2, uint32_t a3,
                                         uint32_t b0, uint32_t b1) {
    asm("mma.sync.aligned.m16n8k16.row.col.f32.bf16.bf16.f32 "
        "{%0,%1,%2,%3}, {%4,%5,%6,%7}, {%8,%9}, {%0,%1,%2,%3};"
        : "+f"(c0), "+f"(c1), "+f"(c2), "+f"(c3)
        : "r"(a0), "r"(a1), "r"(a2), "r"(a3), "r"(b0), "r"(b1));
}

// pack (v0, v1) -> bf16x2 hi, and residual bf16x2 lo. bf16->f32 via bit ops (no cvt).
__device__ __forceinline__ void split2(float v0, float v1, uint32_t& hi2, uint32_t& lo2) {
    __nv_bfloat162 hp = __floats2bfloat162_rn(v0, v1);   // .x = v0 (low 16 bits)
    uint32_t h = *reinterpret_cast<uint32_t*>(&hp);
    float hf0 = __uint_as_float(h << 16);
    float hf1 = __uint_as_float(h & 0xffff0000u);
    __nv_bfloat162 lp = __floats2bfloat162_rn(v0 - hf0, v1 - hf1);
    hi2 = h;
    lo2 = *reinterpret_cast<uint32_t*>(&lp);
}

__device__ __forceinline__ float bf16w_hi(float w) {
    __nv_bfloat16 h = __float2bfloat16(w);
    return __bfloat162float(h);
}

__global__ void __launch_bounds__(256, 1)
nerf_mlp_kernel(const float* __restrict__ x,
                const float* __restrict__ noise,
                const float* __restrict__ stem_w,
                const float* __restrict__ stem_b,
                const float* __restrict__ Ws,
                const float* __restrict__ bs,
                const float* __restrict__ sigma_w,
                const float* __restrict__ sigma_b,
                const float* __restrict__ rgb_w,
                const float* __restrict__ rgb_b,
                float* __restrict__ out,
                int N, int nTiles) {
    extern __shared__ char sm[];
    uint2*  BHs   = (uint2*)(sm + OFF_BH);
    uint2*  BLs   = (uint2*)(sm + OFF_BL);
    float*  biasS = (float*)(sm + OFF_BIAS);
    float*  stemW = (float*)(sm + OFF_STEMW);
    float*  stemB = (float*)(sm + OFF_STEMB);
    float*  smOut = (float*)(sm + OFF_OUT);

    const int tid  = threadIdx.x;
    const int lane = tid & 31;
    const int wid  = tid >> 5;
    const int c    = lane & 3;        // quad column selector
    const int rq   = lane >> 2;       // row within 8-row group / frag n index

    // ---- one-time weight staging: hi/lo bf16 fragments in per-lane layout ----
    // frag (l, kc, nb, lane): b0 packs W(kc*16+k0 +{0,1}, n), b1 packs +{8,9},
    // with k0 = (lane&3)*2, n = nb*8 + lane>>2.  W(l,k,n): fan_in k, fan_out n.
    for (int fi = tid; fi < 7 * 4 * 8 * 32; fi += 256) {
        int fl   = fi & 31;           // lane slot
        int nb   = (fi >> 5) & 7;
        int kc   = (fi >> 8) & 3;
        int l    = fi >> 10;
        int k0   = (fl & 3) * 2;
        int n    = nb * 8 + (fl >> 2);
        float w[4];
        #pragma unroll
        for (int q = 0; q < 4; q++) {
            int k = kc * 16 + k0 + (q >> 1) * 8 + (q & 1);
            float v;
            if (l < 6)            v = Ws[(l << 12) + (k << 6) + n];
            else if (n < 32)      v = rgb_w[(k << 5) + n];
            else if (n == 32)     v = sigma_w[k];
            else                  v = 0.0f;
            w[q] = v;
        }
        float h0 = bf16w_hi(w[0]), h1 = bf16w_hi(w[1]);
        float h2 = bf16w_hi(w[2]), h3 = bf16w_hi(w[3]);
        __nv_bfloat162 p0 = __floats2bfloat162_rn(h0, h1);
        __nv_bfloat162 p1 = __floats2bfloat162_rn(h2, h3);
        __nv_bfloat162 q0 = __floats2bfloat162_rn(w[0] - h0, w[1] - h1);
        __nv_bfloat162 q1 = __floats2bfloat162_rn(w[2] - h2, w[3] - h3);
        BHs[fi] = make_uint2(*(uint32_t*)&p0, *(uint32_t*)&p1);
        BLs[fi] = make_uint2(*(uint32_t*)&q0, *(uint32_t*)&q1);
    }
    for (int i = tid; i < 7 * 64; i += 256) {
        int l = i >> 6, j = i & 63;
        float v;
        if (l < 6)        v = bs[i];
        else if (j < 32)  v = rgb_b[j];
        else if (j == 32) v = sigma_b[0];
        else              v = 0.0f;
        biasS[i] = v;
    }
    if (tid < 96) stemW[tid] = stem_w[tid];
    if (tid < 32) stemB[tid] = stem_b[tid];
    __syncthreads();

    // per-thread tile-local rows: q=0: mblk0 lo, q=1: mblk0 hi, q=2/3: mblk1
    const int lrow0 = wid * 32 + rq;

    for (int t = blockIdx.x; t < nTiles; t += gridDim.x) {
        const long rowBase = (long)t * TILE_M + lrow0;   // + {0,8,16,24}

        uint32_t AH[2][4][4], AL[2][4][4];

        // ---- build first-layer A fragments directly ----
        #pragma unroll
        for (int m = 0; m < 2; m++) {
            long rl = rowBase + m * 16;
            long rh = rl + 8;
            bool vl = rl < N, vh = rh < N;
            // stem rows' x
            float xl0 = 0, xl1 = 0, xl2 = 0, xh0 = 0, xh1 = 0, xh2 = 0;
            if (vl) { xl0 = x[rl * 3]; xl1 = x[rl * 3 + 1]; xl2 = x[rl * 3 + 2]; }
            if (vh) { xh0 = x[rh * 3]; xh1 = x[rh * 3 + 1]; xh2 = x[rh * 3 + 2]; }
            #pragma unroll
            for (int kc = 0; kc < 2; kc++) {        // stem cols 0..31
                int j0 = kc * 16 + 2 * c;
                #pragma unroll
                for (int half8 = 0; half8 < 2; half8++) {
                    int j = j0 + half8 * 8;
                    float2 w0 = *(const float2*)(stemW + j);
                    float2 w1 = *(const float2*)(stemW + 32 + j);
                    float2 w2 = *(const float2*)(stemW + 64 + j);
                    float2 bb = *(const float2*)(stemB + j);
                    float sl0 = bb.x + xl0 * w0.x + xl1 * w1.x + xl2 * w2.x;
                    float sl1 = bb.y + xl0 * w0.y + xl1 * w1.y + xl2 * w2.y;
                    float sh0 = bb.x + xh0 * w0.x + xh1 * w1.x + xh2 * w2.x;
                    float sh1 = bb.y + xh0 * w0.y + xh1 * w1.y + xh2 * w2.y;
                    split2(sl0, sl1, AH[m][kc][half8 * 2],     AL[m][kc][half8 * 2]);
                    split2(sh0, sh1, AH[m][kc][half8 * 2 + 1], AL[m][kc][half8 * 2 + 1]);
                }
            }
            #pragma unroll
            for (int kc = 2; kc < 4; kc++) {        // noise cols 32..63
                int nc0 = (kc - 2) * 16 + 2 * c;
                #pragma unroll
                for (int half8 = 0; half8 < 2; half8++) {
                    int nc = nc0 + half8 * 8;
                    float2 nl = vl ? *(const float2*)(noise + rl * 32 + nc) : make_float2(0, 0);
                    float2 nh = vh ? *(const float2*)(noise + rh * 32 + nc) : make_float2(0, 0);
                    split2(nl.x, nl.y, AH[m][kc][half8 * 2],     AL[m][kc][half8 * 2]);
                    split2(nh.x, nh.y, AH[m][kc][half8 * 2 + 1], AL[m][kc][half8 * 2 + 1]);
                }
            }
        }

        // ---- 7 layers: acc init with bias; 3-term MMA; ReLU+split epilogue ----
        float acc[2][8][4];
        for (int l = 0; l < 7; l++) {
            #pragma unroll
            for (int nb = 0; nb < 8; nb++) {
                float2 bb = *(const float2*)(biasS + l * 64 + nb * 8 + 2 * c);
                #pragma unroll
                for (int m = 0; m < 2; m++) {
                    acc[m][nb][0] = bb.x; acc[m][nb][1] = bb.y;
                    acc[m][nb][2] = bb.x; acc[m][nb][3] = bb.y;
                }
            }
            #pragma unroll
            for (int kc = 0; kc < 4; kc++) {
                const uint2* ph = BHs + ((l * 4 + kc) * 8) * 32 + lane;
                const uint2* pl = BLs + ((l * 4 + kc) * 8) * 32 + lane;
                uint2 bh[8], bl[8];
                #pragma unroll
                for (int nb = 0; nb < 8; nb++) { bh[nb] = ph[nb * 32]; bl[nb] = pl[nb * 32]; }
                #pragma unroll
                for (int nb = 0; nb < 8; nb++)
                    #pragma unroll
                    for (int m = 0; m < 2; m++)
                        mma_bf16(acc[m][nb][0], acc[m][nb][1], acc[m][nb][2], acc[m][nb][3],
                                 AH[m][kc][0], AH[m][kc][1], AH[m][kc][2], AH[m][kc][3],
                                 bh[nb].x, bh[nb].y);
                #pragma unroll
                for (int nb = 0; nb < 8; nb++)
                    #pragma unroll
                    for (int m = 0; m < 2; m++)
                        mma_bf16(acc[m][nb][0], acc[m][nb][1], acc[m][nb][2], acc[m][nb][3],
                                 AH[m][kc][0], AH[m][kc][1], AH[m][kc][2], AH[m][kc][3],
                                 bl[nb].x, bl[nb].y);
                #pragma unroll
                for (int nb = 0; nb < 8; nb++)
                    #pragma unroll
                    for (int m = 0; m < 2; m++)
                        mma_bf16(acc[m][nb][0], acc[m][nb][1], acc[m][nb][2], acc[m][nb][3],
                                 AL[m][kc][0], AL[m][kc][1], AL[m][kc][2], AL[m][kc][3],
                                 bh[nb].x, bh[nb].y);
            }
            if (l < 6) {
                // C-frag (nb pair 2kc,2kc+1) -> A-frag kc, with ReLU
                #pragma unroll
                for (int m = 0; m < 2; m++)
                    #pragma unroll
                    for (int kc = 0; kc < 4; kc++) {
                        float p0 = fmaxf(acc[m][2 * kc][0], 0.f);
                        float p1 = fmaxf(acc[m][2 * kc][1], 0.f);
                        float p2 = fmaxf(acc[m][2 * kc][2], 0.f);
                        float p3 = fmaxf(acc[m][2 * kc][3], 0.f);
                        float q0 = fmaxf(acc[m][2 * kc + 1][0], 0.f);
                        float q1 = fmaxf(acc[m][2 * kc + 1][1], 0.f);
                        float q2 = fmaxf(acc[m][2 * kc + 1][2], 0.f);
                        float q3 = fmaxf(acc[m][2 * kc + 1][3], 0.f);
                        split2(p0, p1, AH[m][kc][0], AL[m][kc][0]);
                        split2(p2, p3, AH[m][kc][1], AL[m][kc][1]);
                        split2(q0, q1, AH[m][kc][2], AL[m][kc][2]);
                        split2(q2, q3, AH[m][kc][3], AL[m][kc][3]);
                    }
            }
        }

        // ---- head epilogue: stage rgb (cols<32) + sigma (col 32) per-warp, coalesced STG ----
        #pragma unroll
        for (int m = 0; m < 2; m++) {
            int rl = lrow0 + m * 16;   // tile-local
            int rh = rl + 8;
            #pragma unroll
            for (int nb = 0; nb < 4; nb++) {
                int j = nb * 8 + 2 * c;
                smOut[rl * 33 + j]     = acc[m][nb][0];
                smOut[rl * 33 + j + 1] = acc[m][nb][1];
                smOut[rh * 33 + j]     = acc[m][nb][2];
                smOut[rh * 33 + j + 1] = acc[m][nb][3];
            }
            if (c == 0) {
                smOut[rl * 33 + 32] = acc[m][4][0];
                smOut[rh * 33 + 32] = acc[m][4][2];
            }
        }
        __syncwarp();
        {
            long gBase = (long)t * (TILE_M * 33) + (long)wid * (32 * 33);
            int  sBase = wid * (32 * 33);
            long rowsLeft = N - (long)t * TILE_M - wid * 32;   // rows this warp owns
            int nfl = 32 * 33;
            if (rowsLeft < 32) nfl = rowsLeft > 0 ? (int)rowsLeft * 33 : 0;
            for (int i = lane; i < nfl; i += 32)
                out[gBase + i] = smOut[sBase + i];
        }
        __syncwarp();
    }
}

extern "C" void kernel_launch(void* const* d_in, const int* in_sizes, int n_in,
                              void* d_out, int out_size) {
    const float* x       = (const float*)d_in[0];
    const float* noise   = (const float*)d_in[1];
    const float* stem_w  = (const float*)d_in[2];
    const float* stem_b  = (const float*)d_in[3];
    const float* Ws      = (const float*)d_in[4];
    const float* bs      = (const float*)d_in[5];
    const float* sigma_w = (const float*)d_in[6];
    const float* sigma_b = (const float*)d_in[7];
    const float* rgb_w   = (const float*)d_in[8];
    const float* rgb_b   = (const float*)d_in[9];
    float* out = (float*)d_out;

    int N = in_sizes[0] / 3;
    int nTiles = (N + TILE_M - 1) / TILE_M;   // 2,097,152 / 256 = 8192

    cudaFuncSetAttribute(nerf_mlp_kernel,
                         cudaFuncAttributeMaxDynamicSharedMemorySize, SMEM_BYTES);

    int dev = 0, sms = 148;
    cudaGetDevice(&dev);
    cudaDeviceGetAttribute(&sms, cudaDevAttrMultiProcessorCount, dev);
    int grid = nTiles < sms ? nTiles : sms;

    nerf_mlp_kernel<<<grid, 256, SMEM_BYTES>>>(
        x, noise, stem_w, stem_b, Ws, bs, sigma_w, sigma_b, rgb_w, rgb_b,
        out, N, nTiles);
}

// round 9
// speedup vs baseline: 2.0894x; 2.0894x over previous
// NerfMLP on GB300 (sm_103a HW, compute_103 PTX target -> legacy HMMA only).
// Round 7: 1-term fp16 MMA (was 3-term bf16 split) -- 3x fewer HMMA.
//  - mma.sync.aligned.m16n8k16.row.col.f32.f16.f16.f32, fp32 accumulators
//  - accuracy budget: fp16 RN ~2.8e-4/layer RMS, predicted end-to-end ~1-3e-4
//  - activations stay in registers across all 7 layers (C-frag == A-frag layout)
//  - bias folded into accumulator init; epilogue = ReLU + f32x2->f16x2 pack only
//  - weights pre-staged once per CTA in SMEM in per-lane fragment layout
//  - 512 threads / 16 warps (4 per SMSP) for issue overlap; warp owns 16 rows x 64 cols
//  - persistent CTAs, tile M=256, no __syncthreads in the tile loop

#include <cuda_runtime.h>
#include <cuda_fp16.h>
#include <cstdint>

#define TILE_M 256

// SMEM layout (bytes)
#define OFF_W     0          // uint2 Wfrag[7*4*8*32] = 57344
#define OFF_BIAS  57344      // float [7*64]          = 1792
#define OFF_STEMW 59136      // float [96]            = 384
#define OFF_STEMB 59520      // float [32]            = 128
#define OFF_OUT   59648      // float [256*33]        = 33792
#define SMEM_BYTES 93440

__device__ __forceinline__ void mma_f16(float& c0, float& c1, float& c2, float& c3,
                                        uint32_t a0, uint32_t a1, uint32_t a2, uint32_t a3,
                                        uint32_t b0, uint32_t b1) {
    asm("mma.sync.aligned.m16n8k16.row.col.f32.f16.f16.f32 "
        "{%0,%1,%2,%3}, {%4,%5,%6,%7}, {%8,%9}, {%0,%1,%2,%3};"
        : "+f"(c0), "+f"(c1), "+f"(c2), "+f"(c3)
        : "r"(a0), "r"(a1), "r"(a2), "r"(a3), "r"(b0), "r"(b1));
}

__device__ __forceinline__ uint32_t pack_h2(float v0, float v1) {
    __half2 p = __floats2half2_rn(v0, v1);
    return *reinterpret_cast<uint32_t*>(&p);
}

__global__ void __launch_bounds__(512, 1)
nerf_mlp_kernel(const float* __restrict__ x,
                const float* __restrict__ noise,
                const float* __restrict__ stem_w,
                const float* __restrict__ stem_b,
                const float* __restrict__ Ws,
                const float* __restrict__ bs,
                const float* __restrict__ sigma_w,
                const float* __restrict__ sigma_b,
                const float* __restrict__ rgb_w,
                const float* __restrict__ rgb_b,
                float* __restrict__ out,
                int N, int nTiles) {
    extern __shared__ char sm[];
    uint2*  Wfr   = (uint2*)(sm + OFF_W);
    float*  biasS = (float*)(sm + OFF_BIAS);
    float*  stemW = (float*)(sm + OFF_STEMW);
    float*  stemB = (float*)(sm + OFF_STEMB);
    float*  smOut = (float*)(sm + OFF_OUT);

    const int tid  = threadIdx.x;
    const int lane = tid & 31;
    const int wid  = tid >> 5;          // 0..15
    const int c    = lane & 3;          // quad column selector
    const int rq   = lane >> 2;         // row-in-8 / B-frag n index

    // ---- one-time weight staging: fp16 fragments in per-lane layout ----
    // frag (l, kc, nb, lane): b0 packs W(kc*16 + 2*(lane&3) + {0,1}, n),
    // b1 packs +8 in k, with n = nb*8 + lane>>2.
    for (int fi = tid; fi < 7 * 4 * 8 * 32; fi += 512) {
        int fl = fi & 31;
        int nb = (fi >> 5) & 7;
        int kc = (fi >> 8) & 3;
        int l  = fi >> 10;
        int k0 = (fl & 3) * 2;
        int n  = nb * 8 + (fl >> 2);
        float w[4];
        #pragma unroll
        for (int q = 0; q < 4; q++) {
            int k = kc * 16 + k0 + (q >> 1) * 8 + (q & 1);
            float v;
            if (l < 6)        v = Ws[(l << 12) + (k << 6) + n];
            else if (n < 32)  v = rgb_w[(k << 5) + n];
            else if (n == 32) v = sigma_w[k];
            else              v = 0.0f;
            w[q] = v;
        }
        Wfr[fi] = make_uint2(pack_h2(w[0], w[1]), pack_h2(w[2], w[3]));
    }
    for (int i = tid; i < 7 * 64; i += 512) {
        int l = i >> 6, j = i & 63;
        float v;
        if (l < 6)        v = bs[i];
        else if (j < 32)  v = rgb_b[j];
        else if (j == 32) v = sigma_b[0];
        else              v = 0.0f;
        biasS[i] = v;
    }
    if (tid < 96) stemW[tid] = stem_w[tid];
    if (tid < 32) stemB[tid] = stem_b[tid];
    __syncthreads();

    const int lrow = wid * 16 + rq;     // tile-local row (this thread: lrow, lrow+8)

    for (int t = blockIdx.x; t < nTiles; t += gridDim.x) {
        const long rl = (long)t * TILE_M + lrow;
        const long rh = rl + 8;
        const bool vl = rl < N, vh = rh < N;

        uint32_t A[4][4];   // A-fragments: [kc][a0..a3], fp16x2

        // ---- first-layer input: concat(stem(x), noise), packed to fp16 frags ----
        {
            float xl0 = 0, xl1 = 0, xl2 = 0, xh0 = 0, xh1 = 0, xh2 = 0;
            if (vl) { xl0 = x[rl * 3]; xl1 = x[rl * 3 + 1]; xl2 = x[rl * 3 + 2]; }
            if (vh) { xh0 = x[rh * 3]; xh1 = x[rh * 3 + 1]; xh2 = x[rh * 3 + 2]; }
            #pragma unroll
            for (int kc = 0; kc < 2; kc++) {          // stem cols 0..31
                #pragma unroll
                for (int h8 = 0; h8 < 2; h8++) {
                    int j = kc * 16 + 2 * c + h8 * 8;
                    float2 w0 = *(const float2*)(stemW + j);
                    float2 w1 = *(const float2*)(stemW + 32 + j);
                    float2 w2 = *(const float2*)(stemW + 64 + j);
                    float2 bb = *(const float2*)(stemB + j);
                    float sl0 = bb.x + xl0 * w0.x + xl1 * w1.x + xl2 * w2.x;
                    float sl1 = bb.y + xl0 * w0.y + xl1 * w1.y + xl2 * w2.y;
                    float sh0 = bb.x + xh0 * w0.x + xh1 * w1.x + xh2 * w2.x;
                    float sh1 = bb.y + xh0 * w0.y + xh1 * w1.y + xh2 * w2.y;
                    A[kc][h8 * 2]     = pack_h2(sl0, sl1);
                    A[kc][h8 * 2 + 1] = pack_h2(sh0, sh1);
                }
            }
            #pragma unroll
            for (int kc = 2; kc < 4; kc++) {          // noise cols 32..63
                #pragma unroll
                for (int h8 = 0; h8 < 2; h8++) {
                    int nc = (kc - 2) * 16 + 2 * c + h8 * 8;
                    float2 nl = vl ? *(const float2*)(noise + rl * 32 + nc) : make_float2(0, 0);
                    float2 nh = vh ? *(const float2*)(noise + rh * 32 + nc) : make_float2(0, 0);
                    A[kc][h8 * 2]     = pack_h2(nl.x, nl.y);
                    A[kc][h8 * 2 + 1] = pack_h2(nh.x, nh.y);
                }
            }
        }

        // ---- 7 layers ----
        float acc[8][4];
        for (int l = 0; l < 7; l++) {
            #pragma unroll
            for (int nb = 0; nb < 8; nb++) {
                float2 bb = *(const float2*)(biasS + l * 64 + nb * 8 + 2 * c);
                acc[nb][0] = bb.x; acc[nb][1] = bb.y;
                acc[nb][2] = bb.x; acc[nb][3] = bb.y;
            }
            #pragma unroll
            for (int kc = 0; kc < 4; kc++) {
                const uint2* pw = Wfr + ((l * 4 + kc) * 8) * 32 + lane;
                uint2 bfr[8];
                #pragma unroll
                for (int nb = 0; nb < 8; nb++) bfr[nb] = pw[nb * 32];
                #pragma unroll
                for (int nb = 0; nb < 8; nb++)
                    mma_f16(acc[nb][0], acc[nb][1], acc[nb][2], acc[nb][3],
                            A[kc][0], A[kc][1], A[kc][2], A[kc][3],
                            bfr[nb].x, bfr[nb].y);
            }
            if (l < 6) {
                // C-frag (nb pair 2kc, 2kc+1) -> next-layer A-frag kc, with ReLU
                #pragma unroll
                for (int kc = 0; kc < 4; kc++) {
                    A[kc][0] = pack_h2(fmaxf(acc[2 * kc][0], 0.f), fmaxf(acc[2 * kc][1], 0.f));
                    A[kc][1] = pack_h2(fmaxf(acc[2 * kc][2], 0.f), fmaxf(acc[2 * kc][3], 0.f));
                    A[kc][2] = pack_h2(fmaxf(acc[2 * kc + 1][0], 0.f), fmaxf(acc[2 * kc + 1][1], 0.f));
                    A[kc][3] = pack_h2(fmaxf(acc[2 * kc + 1][2], 0.f), fmaxf(acc[2 * kc + 1][3], 0.f));
                }
            }
        }

        // ---- head epilogue: stage rgb (cols 0..31) + sigma (col 32) per-warp ----
        {
            int sl = lrow, sh = lrow + 8;   // tile-local rows
            #pragma unroll
            for (int nb = 0; nb < 4; nb++) {
                int j = nb * 8 + 2 * c;
                smOut[sl * 33 + j]     = acc[nb][0];
                smOut[sl * 33 + j + 1] = acc[nb][1];
                smOut[sh * 33 + j]     = acc[nb][2];
                smOut[sh * 33 + j + 1] = acc[nb][3];
            }
            if (c == 0) {
                smOut[sl * 33 + 32] = acc[4][0];
                smOut[sh * 33 + 32] = acc[4][2];
            }
        }
        __syncwarp();
        {
            long gBase = (long)t * (TILE_M * 33) + (long)wid * (16 * 33);
            int  sBase = wid * (16 * 33);
            long rowsLeft = N - (long)t * TILE_M - wid * 16;
            int nfl = 16 * 33;
            if (rowsLeft < 16) nfl = rowsLeft > 0 ? (int)rowsLeft * 33 : 0;
            for (int i = lane; i < nfl; i += 32)
                out[gBase + i] = smOut[sBase + i];
        }
        __syncwarp();
    }
}

extern "C" void kernel_launch(void* const* d_in, const int* in_sizes, int n_in,
                              void* d_out, int out_size) {
    const float* x       = (const float*)d_in[0];
    const float* noise   = (const float*)d_in[1];
    const float* stem_w  = (const float*)d_in[2];
    const float* stem_b  = (const float*)d_in[3];
    const float* Ws      = (const float*)d_in[4];
    const float* bs      = (const float*)d_in[5];
    const float* sigma_w = (const float*)d_in[6];
    const float* sigma_b = (const float*)d_in[7];
    const float* rgb_w   = (const float*)d_in[8];
    const float* rgb_b   = (const float*)d_in[9];
    float* out = (float*)d_out;

    int N = in_sizes[0] / 3;
    int nTiles = (N + TILE_M - 1) / TILE_M;   // 2,097,152 / 256 = 8192

    cudaFuncSetAttribute(nerf_mlp_kernel,
                         cudaFuncAttributeMaxDynamicSharedMemorySize, SMEM_BYTES);

    int dev = 0, sms = 148;
    cudaGetDevice(&dev);
    cudaDeviceGetAttribute(&sms, cudaDevAttrMultiProcessorCount, dev);
    int grid = nTiles < sms ? nTiles : sms;

    nerf_mlp_kernel<<<grid, 512, SMEM_BYTES>>>(
        x, noise, stem_w, stem_b, Ws, bs, sigma_w, sigma_b, rgb_w, rgb_b,
        out, N, nTiles);
}

// round 13
// speedup vs baseline: 2.5763x; 1.2330x over previous
// NerfMLP on GB300 (sm_103a HW, compute_103 PTX target -> legacy HMMA only).
// Round 9: 1-term fp16 MMA + 2 m-blocks per warp (halve LDS per MMA).
//  - R8 finding: L1/smem crossbar at 93% was capping tensor at 54%.
//    1 LDS.64 per HMMA = 1.08 crossbar-cyc/cyc demand -> over capacity.
//  - Fix: warp owns 32 rows (2 m-blocks); each weight fragment LDS serves 2 MMAs.
//  - 384 threads / 12 warps (3 per SMSP), TILE_M=384, ~140 regs (fits 170 budget).
//  - mma.sync.m16n8k16.f32.f16.f16.f32, bias in acc init, ReLU+pack epilogue.
//  - persistent CTAs, no __syncthreads in tile loop.

#include <cuda_runtime.h>
#include <cuda_fp16.h>
#include <cstdint>

#define TILE_M 384

// SMEM layout (bytes)
#define OFF_W     0          // uint2 Wfrag[7*4*8*32] = 57344
#define OFF_BIAS  57344      // float [7*64]          = 1792
#define OFF_STEMW 59136      // float [96]            = 384
#define OFF_STEMB 59520      // float [32]            = 128
#define OFF_OUT   59648      // float [384*33]        = 50688
#define SMEM_BYTES 110336

__device__ __forceinline__ void mma_f16(float& c0, float& c1, float& c2, float& c3,
                                        uint32_t a0, uint32_t a1, uint32_t a2, uint32_t a3,
                                        uint32_t b0, uint32_t b1) {
    asm("mma.sync.aligned.m16n8k16.row.col.f32.f16.f16.f32 "
        "{%0,%1,%2,%3}, {%4,%5,%6,%7}, {%8,%9}, {%0,%1,%2,%3};"
        : "+f"(c0), "+f"(c1), "+f"(c2), "+f"(c3)
        : "r"(a0), "r"(a1), "r"(a2), "r"(a3), "r"(b0), "r"(b1));
}

__device__ __forceinline__ uint32_t pack_h2(float v0, float v1) {
    __half2 p = __floats2half2_rn(v0, v1);
    return *reinterpret_cast<uint32_t*>(&p);
}

__global__ void __launch_bounds__(384, 1)
nerf_mlp_kernel(const float* __restrict__ x,
                const float* __restrict__ noise,
                const float* __restrict__ stem_w,
                const float* __restrict__ stem_b,
                const float* __restrict__ Ws,
                const float* __restrict__ bs,
                const float* __restrict__ sigma_w,
                const float* __restrict__ sigma_b,
                const float* __restrict__ rgb_w,
                const float* __restrict__ rgb_b,
                float* __restrict__ out,
                int N, int nTiles) {
    extern __shared__ char sm[];
    uint2*  Wfr   = (uint2*)(sm + OFF_W);
    float*  biasS = (float*)(sm + OFF_BIAS);
    float*  stemW = (float*)(sm + OFF_STEMW);
    float*  stemB = (float*)(sm + OFF_STEMB);
    float*  smOut = (float*)(sm + OFF_OUT);

    const int tid  = threadIdx.x;
    const int lane = tid & 31;
    const int wid  = tid >> 5;          // 0..11
    const int c    = lane & 3;          // quad column selector
    const int rq   = lane >> 2;         // row-in-8 / B-frag n index

    // ---- one-time weight staging: fp16 fragments in per-lane layout ----
    // frag (l, kc, nb, lane): b0 packs W(kc*16 + 2*(lane&3) + {0,1}, n),
    // b1 packs +8 in k, with n = nb*8 + lane>>2.
    for (int fi = tid; fi < 7 * 4 * 8 * 32; fi += 384) {
        int fl = fi & 31;
        int nb = (fi >> 5) & 7;
        int kc = (fi >> 8) & 3;
        int l  = fi >> 10;
        int k0 = (fl & 3) * 2;
        int n  = nb * 8 + (fl >> 2);
        float w[4];
        #pragma unroll
        for (int q = 0; q < 4; q++) {
            int k = kc * 16 + k0 + (q >> 1) * 8 + (q & 1);
            float v;
            if (l < 6)        v = Ws[(l << 12) + (k << 6) + n];
            else if (n < 32)  v = rgb_w[(k << 5) + n];
            else if (n == 32) v = sigma_w[k];
            else              v = 0.0f;
            w[q] = v;
        }
        Wfr[fi] = make_uint2(pack_h2(w[0], w[1]), pack_h2(w[2], w[3]));
    }
    for (int i = tid; i < 7 * 64; i += 384) {
        int l = i >> 6, j = i & 63;
        float v;
        if (l < 6)        v = bs[i];
        else if (j < 32)  v = rgb_b[j];
        else if (j == 32) v = sigma_b[0];
        else              v = 0.0f;
        biasS[i] = v;
    }
    if (tid < 96) stemW[tid] = stem_w[tid];
    if (tid < 32) stemB[tid] = stem_b[tid];
    __syncthreads();

    // warp owns 32 rows: thread rows = lrow0 + {0,8,16,24} (m-block*16 + {0,8})
    const int lrow0 = wid * 32 + rq;

    for (int t = blockIdx.x; t < nTiles; t += gridDim.x) {
        const long rowBase = (long)t * TILE_M + lrow0;

        uint32_t A[2][4][4];   // [m-block][kc][a0..a3], fp16x2

        // ---- first-layer input: concat(stem(x), noise) -> fp16 A frags ----
        #pragma unroll
        for (int m = 0; m < 2; m++) {
            long rl = rowBase + m * 16;
            long rh = rl + 8;
            bool vl = rl < N, vh = rh < N;
            float xl0 = 0, xl1 = 0, xl2 = 0, xh0 = 0, xh1 = 0, xh2 = 0;
            if (vl) { xl0 = x[rl * 3]; xl1 = x[rl * 3 + 1]; xl2 = x[rl * 3 + 2]; }
            if (vh) { xh0 = x[rh * 3]; xh1 = x[rh * 3 + 1]; xh2 = x[rh * 3 + 2]; }
            #pragma unroll
            for (int kc = 0; kc < 2; kc++) {          // stem cols 0..31
                #pragma unroll
                for (int h8 = 0; h8 < 2; h8++) {
                    int j = kc * 16 + 2 * c + h8 * 8;
                    float2 w0 = *(const float2*)(stemW + j);
                    float2 w1 = *(const float2*)(stemW + 32 + j);
                    float2 w2 = *(const float2*)(stemW + 64 + j);
                    float2 bb = *(const float2*)(stemB + j);
                    float sl0 = bb.x + xl0 * w0.x + xl1 * w1.x + xl2 * w2.x;
                    float sl1 = bb.y + xl0 * w0.y + xl1 * w1.y + xl2 * w2.y;
                    float sh0 = bb.x + xh0 * w0.x + xh1 * w1.x + xh2 * w2.x;
                    float sh1 = bb.y + xh0 * w0.y + xh1 * w1.y + xh2 * w2.y;
                    A[m][kc][h8 * 2]     = pack_h2(sl0, sl1);
                    A[m][kc][h8 * 2 + 1] = pack_h2(sh0, sh1);
                }
            }
            #pragma unroll
            for (int kc = 2; kc < 4; kc++) {          // noise cols 32..63
                #pragma unroll
                for (int h8 = 0; h8 < 2; h8++) {
                    int nc = (kc - 2) * 16 + 2 * c + h8 * 8;
                    float2 nl = vl ? *(const float2*)(noise + rl * 32 + nc) : make_float2(0, 0);
                    float2 nh = vh ? *(const float2*)(noise + rh * 32 + nc) : make_float2(0, 0);
                    A[m][kc][h8 * 2]     = pack_h2(nl.x, nl.y);
                    A[m][kc][h8 * 2 + 1] = pack_h2(nh.x, nh.y);
                }
            }
        }

        // ---- 7 layers: one weight LDS serves both m-blocks ----
        float acc[2][8][4];
        for (int l = 0; l < 7; l++) {
            #pragma unroll
            for (int nb = 0; nb < 8; nb++) {
                float2 bb = *(const float2*)(biasS + l * 64 + nb * 8 + 2 * c);
                #pragma unroll
                for (int m = 0; m < 2; m++) {
                    acc[m][nb][0] = bb.x; acc[m][nb][1] = bb.y;
                    acc[m][nb][2] = bb.x; acc[m][nb][3] = bb.y;
                }
            }
            #pragma unroll
            for (int kc = 0; kc < 4; kc++) {
                const uint2* pw = Wfr + ((l * 4 + kc) * 8) * 32 + lane;
                uint2 bfr[8];
                #pragma unroll
                for (int nb = 0; nb < 8; nb++) bfr[nb] = pw[nb * 32];
                #pragma unroll
                for (int nb = 0; nb < 8; nb++) {
                    mma_f16(acc[0][nb][0], acc[0][nb][1], acc[0][nb][2], acc[0][nb][3],
                            A[0][kc][0], A[0][kc][1], A[0][kc][2], A[0][kc][3],
                            bfr[nb].x, bfr[nb].y);
                    mma_f16(acc[1][nb][0], acc[1][nb][1], acc[1][nb][2], acc[1][nb][3],
                            A[1][kc][0], A[1][kc][1], A[1][kc][2], A[1][kc][3],
                            bfr[nb].x, bfr[nb].y);
                }
            }
            if (l < 6) {
                // C-frag (nb pair 2kc, 2kc+1) -> next-layer A-frag kc, with ReLU
                #pragma unroll
                for (int m = 0; m < 2; m++)
                    #pragma unroll
                    for (int kc = 0; kc < 4; kc++) {
                        A[m][kc][0] = pack_h2(fmaxf(acc[m][2 * kc][0], 0.f),
                                              fmaxf(acc[m][2 * kc][1], 0.f));
                        A[m][kc][1] = pack_h2(fmaxf(acc[m][2 * kc][2], 0.f),
                                              fmaxf(acc[m][2 * kc][3], 0.f));
                        A[m][kc][2] = pack_h2(fmaxf(acc[m][2 * kc + 1][0], 0.f),
                                              fmaxf(acc[m][2 * kc + 1][1], 0.f));
                        A[m][kc][3] = pack_h2(fmaxf(acc[m][2 * kc + 1][2], 0.f),
                                              fmaxf(acc[m][2 * kc + 1][3], 0.f));
                    }
            }
        }

        // ---- head epilogue: stage rgb (cols 0..31) + sigma (col 32) per-warp ----
        #pragma unroll
        for (int m = 0; m < 2; m++) {
            int sl = lrow0 + m * 16;     // tile-local rows
            int sh = sl + 8;
            #pragma unroll
            for (int nb = 0; nb < 4; nb++) {
                int j = nb * 8 + 2 * c;
                smOut[sl * 33 + j]     = acc[m][nb][0];
                smOut[sl * 33 + j + 1] = acc[m][nb][1];
                smOut[sh * 33 + j]     = acc[m][nb][2];
                smOut[sh * 33 + j + 1] = acc[m][nb][3];
            }
            if (c == 0) {
                smOut[sl * 33 + 32] = acc[m][4][0];
                smOut[sh * 33 + 32] = acc[m][4][2];
            }
        }
        __syncwarp();
        {
            long gBase = (long)t * (TILE_M * 33) + (long)wid * (32 * 33);
            int  sBase = wid * (32 * 33);
            long rowsLeft = N - (long)t * TILE_M - wid * 32;
            int nfl = 32 * 33;
            if (rowsLeft < 32) nfl = rowsLeft > 0 ? (int)rowsLeft * 33 : 0;
            for (int i = lane; i < nfl; i += 32)
                out[gBase + i] = smOut[sBase + i];
        }
        __syncwarp();
    }
}

extern "C" void kernel_launch(void* const* d_in, const int* in_sizes, int n_in,
                              void* d_out, int out_size) {
    const float* x       = (const float*)d_in[0];
    const float* noise   = (const float*)d_in[1];
    const float* stem_w  = (const float*)d_in[2];
    const float* stem_b  = (const float*)d_in[3];
    const float* Ws      = (const float*)d_in[4];
    const float* bs      = (const float*)d_in[5];
    const float* sigma_w = (const float*)d_in[6];
    const float* sigma_b = (const float*)d_in[7];
    const float* rgb_w   = (const float*)d_in[8];
    const float* rgb_b   = (const float*)d_in[9];
    float* out = (float*)d_out;

    int N = in_sizes[0] / 3;
    int nTiles = (N + TILE_M - 1) / TILE_M;   // ceil(2,097,152 / 384) = 5462

    cudaFuncSetAttribute(nerf_mlp_kernel,
                         cudaFuncAttributeMaxDynamicSharedMemorySize, SMEM_BYTES);

    int dev = 0, sms = 148;
    cudaGetDevice(&dev);
    cudaDeviceGetAttribute(&sms, cudaDevAttrMultiProcessorCount, dev);
    int grid = nTiles < sms ? nTiles : sms;

    nerf_mlp_kernel<<<grid, 384, SMEM_BYTES>>>(
        x, noise, stem_w, stem_b, Ws, bs, sigma_w, sigma_b, rgb_w, rgb_b,
        out, N, nTiles);
}